// round 1
// baseline (speedup 1.0000x reference)
#include <cuda_runtime.h>
#include <cstdint>

// ---------------------------------------------------------------------------
// EncoderLayer: x -> MHA -> add&LN -> FF(relu) -> add&LN
// B=4, S=2048, D=1024, H=16, hd=64, FF=4096, fp32 in/out.
// Strategy: one generic tf32 mma.m16n8k8 tiled GEMM used for all matmuls,
// plus softmax-row and fused add+LayerNorm kernels. Scratch in __device__
// globals (no allocation allowed).
// ---------------------------------------------------------------------------

namespace cfg {
constexpr int D_MODEL = 1024;
constexpr int NHEADS  = 16;
constexpr int HDIM    = 64;
constexpr int DFF     = 4096;
constexpr int BATCH   = 4;
constexpr int SEQ     = 2048;
constexpr int NTOK    = BATCH * SEQ;   // 8192
}

// ------------------------------ scratch ------------------------------------
__device__ float g_q   [(size_t)cfg::NTOK * cfg::D_MODEL];
__device__ float g_k   [(size_t)cfg::NTOK * cfg::D_MODEL];
__device__ float g_v   [(size_t)cfg::NTOK * cfg::D_MODEL];
__device__ float g_sc  [(size_t)cfg::BATCH * cfg::NHEADS * cfg::SEQ * cfg::SEQ]; // 1 GB
__device__ float g_attn[(size_t)cfg::NTOK * cfg::D_MODEL];
__device__ float g_h   [(size_t)cfg::NTOK * cfg::D_MODEL];
__device__ float g_ff  [(size_t)cfg::NTOK * cfg::DFF];

// ------------------------------ helpers ------------------------------------
__device__ __forceinline__ uint32_t f2tf32(float f) {
    uint32_t u;
    asm("cvt.rna.tf32.f32 %0, %1;" : "=r"(u) : "f"(f));
    return u;
}

__device__ __forceinline__ void mma_m16n8k8(float* c, const uint32_t* a, const uint32_t* b) {
    asm volatile(
        "mma.sync.aligned.m16n8k8.row.col.f32.tf32.tf32.f32 "
        "{%0,%1,%2,%3}, {%4,%5,%6,%7}, {%8,%9}, {%0,%1,%2,%3};\n"
        : "+f"(c[0]), "+f"(c[1]), "+f"(c[2]), "+f"(c[3])
        : "r"(a[0]), "r"(a[1]), "r"(a[2]), "r"(a[3]),
          "r"(b[0]), "r"(b[1]));
}

// ------------------------------ GEMM ---------------------------------------
// C[M,N] = alpha * A[M,K] @ B + bias, optional ReLU.
// BKMAJOR=false: B element (k,n) at B[k*ldb + n]   (standard K x N row-major)
// BKMAJOR=true : B element (k,n) at B[n*ldb + k]   (N x K row-major, i.e. B^T; for Q@K^T)
// Batched over blockIdx.z decomposed as (b = z/H, h = z%H) with separate strides.
// ALL problem dims here are exact multiples of the tile sizes (asserted by usage).
template <int BM, int BN, int BK, int WM, int WN, bool BKMAJOR, bool RELU>
__global__ void __launch_bounds__(256) gemm_tf32(
    const float* __restrict__ A, const float* __restrict__ B,
    const float* __restrict__ bias, float* __restrict__ C,
    int M, int N, int K, int lda, int ldb, int ldc,
    int H, long long sAb, long long sAh, long long sBb, long long sBh,
    long long sCb, long long sCh, float alpha)
{
    constexpr int WARPS_M = BM / WM;
    constexpr int WARPS_N = BN / WN;
    static_assert(WARPS_M * WARPS_N == 8, "need 8 warps / 256 threads");
    constexpr int MI = WM / 16;
    constexpr int NI = WN / 8;
    // padding for conflict-free fragment reads:
    constexpr int LDAS = BK + 4;   // BK=16 -> 20 (== 4 mod 8 pattern, distinct banks)
    constexpr int LDBS = BN + 8;   // stride % 32 == 8 -> k-quads hit banks {0,8,16,24}+g

    __shared__ float As[2][BM][LDAS];
    __shared__ float Bs[2][BK][LDBS];

    const int tid = threadIdx.x;
    const int bb  = blockIdx.z / H;
    const int hh  = blockIdx.z % H;
    const float* Ag = A + (long long)bb * sAb + (long long)hh * sAh;
    const float* Bg = B + (long long)bb * sBb + (long long)hh * sBh;
    float*       Cg = C + (long long)bb * sCb + (long long)hh * sCh;
    const int bm = blockIdx.y * BM;
    const int bn = blockIdx.x * BN;

    // A tile loader: BM x BK, one float4 (along K) per thread per iter
    constexpr int A_TPR   = BK / 4;          // 4
    constexpr int A_RSTEP = 256 / A_TPR;     // 64
    constexpr int A_ITERS = BM / A_RSTEP;    // 2
    const int a_row = tid / A_TPR;
    const int a_col = (tid % A_TPR) * 4;

    // B tile loader (standard K x N layout)
    constexpr int B_TPR   = BN / 4;
    constexpr int B_RSTEP = 256 / B_TPR;
    constexpr int B_ITERS = BK / B_RSTEP;
    const int b_row = tid / B_TPR;
    const int b_col = (tid % B_TPR) * 4;

    // B tile loader (K-major layout: float4 along K)
    constexpr int T_TPC   = BK / 4;          // 4
    constexpr int T_NSTEP = 256 / T_TPC;     // 64
    constexpr int T_ITERS = BN / T_NSTEP;
    const int t_n = tid / T_TPC;
    const int t_k = (tid % T_TPC) * 4;

    constexpr int B_REGS = BKMAJOR ? T_ITERS : B_ITERS;

    float4 ra[A_ITERS];
    float4 rb[B_REGS];

    auto ldg = [&](int k0) {
        #pragma unroll
        for (int i = 0; i < A_ITERS; i++) {
            int r = a_row + i * A_RSTEP;
            ra[i] = *reinterpret_cast<const float4*>(
                Ag + (long long)(bm + r) * lda + (k0 + a_col));
        }
        if constexpr (BKMAJOR) {
            #pragma unroll
            for (int i = 0; i < B_REGS; i++) {
                int n = t_n + i * T_NSTEP;
                rb[i] = *reinterpret_cast<const float4*>(
                    Bg + (long long)(bn + n) * ldb + (k0 + t_k));
            }
        } else {
            #pragma unroll
            for (int i = 0; i < B_REGS; i++) {
                int r = b_row + i * B_RSTEP;
                rb[i] = *reinterpret_cast<const float4*>(
                    Bg + (long long)(k0 + r) * ldb + (bn + b_col));
            }
        }
    };

    auto sts = [&](int buf) {
        #pragma unroll
        for (int i = 0; i < A_ITERS; i++) {
            int r = a_row + i * A_RSTEP;
            uint32_t* d = reinterpret_cast<uint32_t*>(&As[buf][r][a_col]);
            d[0] = f2tf32(ra[i].x); d[1] = f2tf32(ra[i].y);
            d[2] = f2tf32(ra[i].z); d[3] = f2tf32(ra[i].w);
        }
        if constexpr (BKMAJOR) {
            #pragma unroll
            for (int i = 0; i < B_REGS; i++) {
                int n = t_n + i * T_NSTEP;
                reinterpret_cast<uint32_t&>(Bs[buf][t_k + 0][n]) = f2tf32(rb[i].x);
                reinterpret_cast<uint32_t&>(Bs[buf][t_k + 1][n]) = f2tf32(rb[i].y);
                reinterpret_cast<uint32_t&>(Bs[buf][t_k + 2][n]) = f2tf32(rb[i].z);
                reinterpret_cast<uint32_t&>(Bs[buf][t_k + 3][n]) = f2tf32(rb[i].w);
            }
        } else {
            #pragma unroll
            for (int i = 0; i < B_REGS; i++) {
                int r = b_row + i * B_RSTEP;
                uint32_t* d = reinterpret_cast<uint32_t*>(&Bs[buf][r][b_col]);
                d[0] = f2tf32(rb[i].x); d[1] = f2tf32(rb[i].y);
                d[2] = f2tf32(rb[i].z); d[3] = f2tf32(rb[i].w);
            }
        }
    };

    const int lane = tid & 31;
    const int warp = tid >> 5;
    const int wm   = warp % WARPS_M;
    const int wn   = warp / WARPS_M;
    const int grp  = lane >> 2;   // 0..7
    const int tg   = lane & 3;    // 0..3

    float acc[MI][NI][4];
    #pragma unroll
    for (int mi = 0; mi < MI; mi++)
        #pragma unroll
        for (int ni = 0; ni < NI; ni++)
            #pragma unroll
            for (int j = 0; j < 4; j++) acc[mi][ni][j] = 0.f;

    const int ntiles = K / BK;
    ldg(0);
    sts(0);
    __syncthreads();
    int buf = 0;

    for (int kt = 0; kt < ntiles; kt++) {
        const bool has_next = (kt + 1 < ntiles);
        if (has_next) ldg((kt + 1) * BK);

        #pragma unroll
        for (int kk = 0; kk < BK; kk += 8) {
            uint32_t af[MI][4];
            uint32_t bfr[NI][2];
            #pragma unroll
            for (int mi = 0; mi < MI; mi++) {
                const int r = wm * WM + mi * 16;
                af[mi][0] = __float_as_uint(As[buf][r + grp    ][kk + tg    ]);
                af[mi][1] = __float_as_uint(As[buf][r + grp + 8][kk + tg    ]);
                af[mi][2] = __float_as_uint(As[buf][r + grp    ][kk + tg + 4]);
                af[mi][3] = __float_as_uint(As[buf][r + grp + 8][kk + tg + 4]);
            }
            #pragma unroll
            for (int ni = 0; ni < NI; ni++) {
                const int c = wn * WN + ni * 8 + grp;
                bfr[ni][0] = __float_as_uint(Bs[buf][kk + tg    ][c]);
                bfr[ni][1] = __float_as_uint(Bs[buf][kk + tg + 4][c]);
            }
            #pragma unroll
            for (int mi = 0; mi < MI; mi++)
                #pragma unroll
                for (int ni = 0; ni < NI; ni++)
                    mma_m16n8k8(acc[mi][ni], af[mi], bfr[ni]);
        }

        if (has_next) sts(buf ^ 1);
        __syncthreads();
        buf ^= 1;
    }

    // epilogue (dims are exact multiples of tiles; no guards needed)
    #pragma unroll
    for (int mi = 0; mi < MI; mi++) {
        const int r0 = bm + wm * WM + mi * 16 + grp;
        #pragma unroll
        for (int ni = 0; ni < NI; ni++) {
            const int c0 = bn + wn * WN + ni * 8 + tg * 2;
            float bv0 = 0.f, bv1 = 0.f;
            if (bias) { bv0 = __ldg(&bias[c0]); bv1 = __ldg(&bias[c0 + 1]); }
            float v0 = acc[mi][ni][0] * alpha + bv0;
            float v1 = acc[mi][ni][1] * alpha + bv1;
            float v2 = acc[mi][ni][2] * alpha + bv0;
            float v3 = acc[mi][ni][3] * alpha + bv1;
            if (RELU) {
                v0 = fmaxf(v0, 0.f); v1 = fmaxf(v1, 0.f);
                v2 = fmaxf(v2, 0.f); v3 = fmaxf(v3, 0.f);
            }
            *reinterpret_cast<float2*>(&Cg[(long long)r0 * ldc + c0]) =
                make_float2(v0, v1);
            *reinterpret_cast<float2*>(&Cg[(long long)(r0 + 8) * ldc + c0]) =
                make_float2(v2, v3);
        }
    }
}

// ------------------------------ softmax ------------------------------------
// One block per row of 2048; in-place.
__global__ void __launch_bounds__(256) softmax_rows(float* __restrict__ data) {
    const long long row = blockIdx.x;
    float* p = data + row * (long long)cfg::SEQ;
    const int tid = threadIdx.x;

    float v[8];
    float m = -3.402823466e38f;
    #pragma unroll
    for (int i = 0; i < 8; i++) {
        v[i] = p[i * 256 + tid];
        m = fmaxf(m, v[i]);
    }

    __shared__ float red[8];
    #pragma unroll
    for (int o = 16; o > 0; o >>= 1) m = fmaxf(m, __shfl_xor_sync(0xffffffffu, m, o));
    if ((tid & 31) == 0) red[tid >> 5] = m;
    __syncthreads();
    float bmax = red[0];
    #pragma unroll
    for (int j = 1; j < 8; j++) bmax = fmaxf(bmax, red[j]);
    __syncthreads();

    float s = 0.f;
    #pragma unroll
    for (int i = 0; i < 8; i++) { v[i] = __expf(v[i] - bmax); s += v[i]; }
    #pragma unroll
    for (int o = 16; o > 0; o >>= 1) s += __shfl_xor_sync(0xffffffffu, s, o);
    if ((tid & 31) == 0) red[tid >> 5] = s;
    __syncthreads();
    float tot = 0.f;
    #pragma unroll
    for (int j = 0; j < 8; j++) tot += red[j];

    const float inv = 1.f / tot;
    #pragma unroll
    for (int i = 0; i < 8; i++) p[i * 256 + tid] = v[i] * inv;
}

// ------------------------------ add + LayerNorm ----------------------------
// out[row] = LN(a[row] + b[row]) * gamma + beta, row length = 1024.
__global__ void __launch_bounds__(256) add_ln_kernel(
    const float* __restrict__ a, const float* __restrict__ b,
    const float* __restrict__ gamma, const float* __restrict__ beta,
    float* __restrict__ outp)
{
    const long long row = blockIdx.x;
    const float* pa = a + row * cfg::D_MODEL;
    const float* pb = b + row * cfg::D_MODEL;
    float* po = outp + row * cfg::D_MODEL;
    const int tid = threadIdx.x;

    float v[4];
    float s = 0.f, sq = 0.f;
    #pragma unroll
    for (int i = 0; i < 4; i++) {
        const int c = i * 256 + tid;
        v[i] = pa[c] + pb[c];
        s += v[i];
        sq += v[i] * v[i];
    }

    __shared__ float r1[8], r2[8];
    #pragma unroll
    for (int o = 16; o > 0; o >>= 1) {
        s  += __shfl_xor_sync(0xffffffffu, s, o);
        sq += __shfl_xor_sync(0xffffffffu, sq, o);
    }
    if ((tid & 31) == 0) { r1[tid >> 5] = s; r2[tid >> 5] = sq; }
    __syncthreads();
    s = 0.f; sq = 0.f;
    #pragma unroll
    for (int j = 0; j < 8; j++) { s += r1[j]; sq += r2[j]; }

    const float mu   = s * (1.f / cfg::D_MODEL);
    const float var  = sq * (1.f / cfg::D_MODEL) - mu * mu;
    const float rstd = rsqrtf(var + 1e-5f);

    #pragma unroll
    for (int i = 0; i < 4; i++) {
        const int c = i * 256 + tid;
        po[c] = (v[i] - mu) * rstd * __ldg(&gamma[c]) + __ldg(&beta[c]);
    }
}

// ------------------------------ launch -------------------------------------
extern "C" void kernel_launch(void* const* d_in, const int* in_sizes, int n_in,
                              void* d_out, int out_size)
{
    using namespace cfg;
    const float* x   = (const float*)d_in[0];
    const float* Wq  = (const float*)d_in[1];
    const float* bq  = (const float*)d_in[2];
    const float* Wk  = (const float*)d_in[3];
    const float* bk_ = (const float*)d_in[4];
    const float* Wv  = (const float*)d_in[5];
    const float* bv  = (const float*)d_in[6];
    const float* Wo  = (const float*)d_in[7];
    const float* bo  = (const float*)d_in[8];
    const float* W1  = (const float*)d_in[9];
    const float* b1  = (const float*)d_in[10];
    const float* W2  = (const float*)d_in[11];
    const float* b2  = (const float*)d_in[12];
    const float* g1  = (const float*)d_in[13];
    const float* be1 = (const float*)d_in[14];
    const float* g2  = (const float*)d_in[15];
    const float* be2 = (const float*)d_in[16];
    float* out = (float*)d_out;

    float *q, *k, *v, *sc, *attn, *h, *ff;
    cudaGetSymbolAddress((void**)&q,    g_q);
    cudaGetSymbolAddress((void**)&k,    g_k);
    cudaGetSymbolAddress((void**)&v,    g_v);
    cudaGetSymbolAddress((void**)&sc,   g_sc);
    cudaGetSymbolAddress((void**)&attn, g_attn);
    cudaGetSymbolAddress((void**)&h,    g_h);
    cudaGetSymbolAddress((void**)&ff,   g_ff);

    const long long SD  = (long long)SEQ * D_MODEL;   // per-batch token-block stride
    const long long SS  = (long long)SEQ * SEQ;       // per-head score stride

    // 1) Q/K/V projections: [8192,1024] @ [1024,1024] + bias
    {
        dim3 grid(D_MODEL / 128, NTOK / 128, 1);
        gemm_tf32<128,128,16,64,32,false,false><<<grid, 256>>>(
            x, Wq, bq, q, NTOK, D_MODEL, D_MODEL, D_MODEL, D_MODEL, D_MODEL,
            1, 0, 0, 0, 0, 0, 0, 1.f);
        gemm_tf32<128,128,16,64,32,false,false><<<grid, 256>>>(
            x, Wk, bk_, k, NTOK, D_MODEL, D_MODEL, D_MODEL, D_MODEL, D_MODEL,
            1, 0, 0, 0, 0, 0, 0, 1.f);
        gemm_tf32<128,128,16,64,32,false,false><<<grid, 256>>>(
            x, Wv, bv, v, NTOK, D_MODEL, D_MODEL, D_MODEL, D_MODEL, D_MODEL,
            1, 0, 0, 0, 0, 0, 0, 1.f);
    }

    // 2) scores = (Q @ K^T) / sqrt(64), per (b,h): M=N=2048, K=64
    {
        dim3 grid(SEQ / 128, SEQ / 128, BATCH * NHEADS);
        gemm_tf32<128,128,16,64,32,true,false><<<grid, 256>>>(
            q, k, nullptr, sc, SEQ, SEQ, HDIM, D_MODEL, D_MODEL, SEQ,
            NHEADS, SD, HDIM, SD, HDIM, (long long)NHEADS * SS, SS,
            0.125f);
    }

    // 3) row softmax over 2048-wide rows (64 * 2048 rows)
    softmax_rows<<<BATCH * NHEADS * SEQ, 256>>>(sc);

    // 4) attn = P @ V, per (b,h): M=2048, N=64, K=2048
    {
        dim3 grid(1, SEQ / 128, BATCH * NHEADS);
        gemm_tf32<128,64,16,32,32,false,false><<<grid, 256>>>(
            sc, v, nullptr, attn, SEQ, HDIM, SEQ, SEQ, D_MODEL, D_MODEL,
            NHEADS, (long long)NHEADS * SS, SS, SD, HDIM, SD, HDIM,
            1.f);
    }

    // 5) output projection: attn @ Wo + bo  -> reuse q as scratch
    {
        dim3 grid(D_MODEL / 128, NTOK / 128, 1);
        gemm_tf32<128,128,16,64,32,false,false><<<grid, 256>>>(
            attn, Wo, bo, q, NTOK, D_MODEL, D_MODEL, D_MODEL, D_MODEL, D_MODEL,
            1, 0, 0, 0, 0, 0, 0, 1.f);
    }

    // 6) h = LN(x + proj)
    add_ln_kernel<<<NTOK, 256>>>(x, q, g1, be1, h);

    // 7) ff = relu(h @ W1 + b1)
    {
        dim3 grid(DFF / 128, NTOK / 128, 1);
        gemm_tf32<128,128,16,64,32,false,true><<<grid, 256>>>(
            h, W1, b1, ff, NTOK, DFF, D_MODEL, D_MODEL, DFF, DFF,
            1, 0, 0, 0, 0, 0, 0, 1.f);
    }

    // 8) ff2 = ff @ W2 + b2  -> reuse k as scratch
    {
        dim3 grid(D_MODEL / 128, NTOK / 128, 1);
        gemm_tf32<128,128,16,64,32,false,false><<<grid, 256>>>(
            ff, W2, b2, k, NTOK, D_MODEL, DFF, DFF, D_MODEL, D_MODEL,
            1, 0, 0, 0, 0, 0, 0, 1.f);
    }

    // 9) out = LN(h + ff2)
    add_ln_kernel<<<NTOK, 256>>>(h, k, g2, be2, out);
}

// round 2
// speedup vs baseline: 1.2380x; 1.2380x over previous
#include <cuda_runtime.h>
#include <cstdint>

// ---------------------------------------------------------------------------
// EncoderLayer: x -> MHA(flash) -> add&LN -> FF(relu) -> add&LN
// B=4, S=2048, D=1024, H=16, hd=64, FF=4096, fp32 in/out.
// Round 2: fused flash-attention kernel (no materialized scores buffer).
// ---------------------------------------------------------------------------

namespace cfg {
constexpr int D_MODEL = 1024;
constexpr int NHEADS  = 16;
constexpr int HDIM    = 64;
constexpr int DFF     = 4096;
constexpr int BATCH   = 4;
constexpr int SEQ     = 2048;
constexpr int NTOK    = BATCH * SEQ;   // 8192
}

// ------------------------------ scratch ------------------------------------
__device__ float g_q   [(size_t)cfg::NTOK * cfg::D_MODEL];
__device__ float g_k   [(size_t)cfg::NTOK * cfg::D_MODEL];
__device__ float g_v   [(size_t)cfg::NTOK * cfg::D_MODEL];
__device__ float g_attn[(size_t)cfg::NTOK * cfg::D_MODEL];
__device__ float g_h   [(size_t)cfg::NTOK * cfg::D_MODEL];
__device__ float g_ff  [(size_t)cfg::NTOK * cfg::DFF];

// ------------------------------ helpers ------------------------------------
__device__ __forceinline__ uint32_t f2tf32(float f) {
    uint32_t u;
    asm("cvt.rna.tf32.f32 %0, %1;" : "=r"(u) : "f"(f));
    return u;
}

__device__ __forceinline__ void mma_m16n8k8(float* c, const uint32_t* a, const uint32_t* b) {
    asm volatile(
        "mma.sync.aligned.m16n8k8.row.col.f32.tf32.tf32.f32 "
        "{%0,%1,%2,%3}, {%4,%5,%6,%7}, {%8,%9}, {%0,%1,%2,%3};\n"
        : "+f"(c[0]), "+f"(c[1]), "+f"(c[2]), "+f"(c[3])
        : "r"(a[0]), "r"(a[1]), "r"(a[2]), "r"(a[3]),
          "r"(b[0]), "r"(b[1]));
}

// ------------------------------ GEMM ---------------------------------------
// C[M,N] = alpha * A[M,K] @ B + bias, optional ReLU.
template <int BM, int BN, int BK, int WM, int WN, bool BKMAJOR, bool RELU>
__global__ void __launch_bounds__(256) gemm_tf32(
    const float* __restrict__ A, const float* __restrict__ B,
    const float* __restrict__ bias, float* __restrict__ C,
    int M, int N, int K, int lda, int ldb, int ldc,
    int H, long long sAb, long long sAh, long long sBb, long long sBh,
    long long sCb, long long sCh, float alpha)
{
    constexpr int WARPS_M = BM / WM;
    constexpr int WARPS_N = BN / WN;
    static_assert(WARPS_M * WARPS_N == 8, "need 8 warps / 256 threads");
    constexpr int MI = WM / 16;
    constexpr int NI = WN / 8;
    constexpr int LDAS = BK + 4;
    constexpr int LDBS = BN + 8;

    __shared__ float As[2][BM][LDAS];
    __shared__ float Bs[2][BK][LDBS];

    const int tid = threadIdx.x;
    const int bb  = blockIdx.z / H;
    const int hh  = blockIdx.z % H;
    const float* Ag = A + (long long)bb * sAb + (long long)hh * sAh;
    const float* Bg = B + (long long)bb * sBb + (long long)hh * sBh;
    float*       Cg = C + (long long)bb * sCb + (long long)hh * sCh;
    const int bm = blockIdx.y * BM;
    const int bn = blockIdx.x * BN;

    constexpr int A_TPR   = BK / 4;
    constexpr int A_RSTEP = 256 / A_TPR;
    constexpr int A_ITERS = BM / A_RSTEP;
    const int a_row = tid / A_TPR;
    const int a_col = (tid % A_TPR) * 4;

    constexpr int B_TPR   = BN / 4;
    constexpr int B_RSTEP = 256 / B_TPR;
    constexpr int B_ITERS = BK / B_RSTEP;
    const int b_row = tid / B_TPR;
    const int b_col = (tid % B_TPR) * 4;

    constexpr int T_TPC   = BK / 4;
    constexpr int T_NSTEP = 256 / T_TPC;
    constexpr int T_ITERS = BN / T_NSTEP;
    const int t_n = tid / T_TPC;
    const int t_k = (tid % T_TPC) * 4;

    constexpr int B_REGS = BKMAJOR ? T_ITERS : B_ITERS;

    float4 ra[A_ITERS];
    float4 rb[B_REGS];

    auto ldg = [&](int k0) {
        #pragma unroll
        for (int i = 0; i < A_ITERS; i++) {
            int r = a_row + i * A_RSTEP;
            ra[i] = *reinterpret_cast<const float4*>(
                Ag + (long long)(bm + r) * lda + (k0 + a_col));
        }
        if constexpr (BKMAJOR) {
            #pragma unroll
            for (int i = 0; i < B_REGS; i++) {
                int n = t_n + i * T_NSTEP;
                rb[i] = *reinterpret_cast<const float4*>(
                    Bg + (long long)(bn + n) * ldb + (k0 + t_k));
            }
        } else {
            #pragma unroll
            for (int i = 0; i < B_REGS; i++) {
                int r = b_row + i * B_RSTEP;
                rb[i] = *reinterpret_cast<const float4*>(
                    Bg + (long long)(k0 + r) * ldb + (bn + b_col));
            }
        }
    };

    auto sts = [&](int buf) {
        #pragma unroll
        for (int i = 0; i < A_ITERS; i++) {
            int r = a_row + i * A_RSTEP;
            uint32_t* d = reinterpret_cast<uint32_t*>(&As[buf][r][a_col]);
            d[0] = f2tf32(ra[i].x); d[1] = f2tf32(ra[i].y);
            d[2] = f2tf32(ra[i].z); d[3] = f2tf32(ra[i].w);
        }
        if constexpr (BKMAJOR) {
            #pragma unroll
            for (int i = 0; i < B_REGS; i++) {
                int n = t_n + i * T_NSTEP;
                reinterpret_cast<uint32_t&>(Bs[buf][t_k + 0][n]) = f2tf32(rb[i].x);
                reinterpret_cast<uint32_t&>(Bs[buf][t_k + 1][n]) = f2tf32(rb[i].y);
                reinterpret_cast<uint32_t&>(Bs[buf][t_k + 2][n]) = f2tf32(rb[i].z);
                reinterpret_cast<uint32_t&>(Bs[buf][t_k + 3][n]) = f2tf32(rb[i].w);
            }
        } else {
            #pragma unroll
            for (int i = 0; i < B_REGS; i++) {
                int r = b_row + i * B_RSTEP;
                uint32_t* d = reinterpret_cast<uint32_t*>(&Bs[buf][r][b_col]);
                d[0] = f2tf32(rb[i].x); d[1] = f2tf32(rb[i].y);
                d[2] = f2tf32(rb[i].z); d[3] = f2tf32(rb[i].w);
            }
        }
    };

    const int lane = tid & 31;
    const int warp = tid >> 5;
    const int wm   = warp % WARPS_M;
    const int wn   = warp / WARPS_M;
    const int grp  = lane >> 2;
    const int tg   = lane & 3;

    float acc[MI][NI][4];
    #pragma unroll
    for (int mi = 0; mi < MI; mi++)
        #pragma unroll
        for (int ni = 0; ni < NI; ni++)
            #pragma unroll
            for (int j = 0; j < 4; j++) acc[mi][ni][j] = 0.f;

    const int ntiles = K / BK;
    ldg(0);
    sts(0);
    __syncthreads();
    int buf = 0;

    for (int kt = 0; kt < ntiles; kt++) {
        const bool has_next = (kt + 1 < ntiles);
        if (has_next) ldg((kt + 1) * BK);

        #pragma unroll
        for (int kk = 0; kk < BK; kk += 8) {
            uint32_t af[MI][4];
            uint32_t bfr[NI][2];
            #pragma unroll
            for (int mi = 0; mi < MI; mi++) {
                const int r = wm * WM + mi * 16;
                af[mi][0] = __float_as_uint(As[buf][r + grp    ][kk + tg    ]);
                af[mi][1] = __float_as_uint(As[buf][r + grp + 8][kk + tg    ]);
                af[mi][2] = __float_as_uint(As[buf][r + grp    ][kk + tg + 4]);
                af[mi][3] = __float_as_uint(As[buf][r + grp + 8][kk + tg + 4]);
            }
            #pragma unroll
            for (int ni = 0; ni < NI; ni++) {
                const int c = wn * WN + ni * 8 + grp;
                bfr[ni][0] = __float_as_uint(Bs[buf][kk + tg    ][c]);
                bfr[ni][1] = __float_as_uint(Bs[buf][kk + tg + 4][c]);
            }
            #pragma unroll
            for (int mi = 0; mi < MI; mi++)
                #pragma unroll
                for (int ni = 0; ni < NI; ni++)
                    mma_m16n8k8(acc[mi][ni], af[mi], bfr[ni]);
        }

        if (has_next) sts(buf ^ 1);
        __syncthreads();
        buf ^= 1;
    }

    #pragma unroll
    for (int mi = 0; mi < MI; mi++) {
        const int r0 = bm + wm * WM + mi * 16 + grp;
        #pragma unroll
        for (int ni = 0; ni < NI; ni++) {
            const int c0 = bn + wn * WN + ni * 8 + tg * 2;
            float bv0 = 0.f, bv1 = 0.f;
            if (bias) { bv0 = __ldg(&bias[c0]); bv1 = __ldg(&bias[c0 + 1]); }
            float v0 = acc[mi][ni][0] * alpha + bv0;
            float v1 = acc[mi][ni][1] * alpha + bv1;
            float v2 = acc[mi][ni][2] * alpha + bv0;
            float v3 = acc[mi][ni][3] * alpha + bv1;
            if (RELU) {
                v0 = fmaxf(v0, 0.f); v1 = fmaxf(v1, 0.f);
                v2 = fmaxf(v2, 0.f); v3 = fmaxf(v3, 0.f);
            }
            *reinterpret_cast<float2*>(&Cg[(long long)r0 * ldc + c0]) =
                make_float2(v0, v1);
            *reinterpret_cast<float2*>(&Cg[(long long)(r0 + 8) * ldc + c0]) =
                make_float2(v2, v3);
        }
    }
}

// --------------------------- flash attention --------------------------------
// One CTA = 128 Q rows of one (b,h). 8 warps x 16 rows. KV tiles of 64.
// Q pre-scaled by 1/sqrt(64), persistent in registers as tf32 A-fragments.
// Online softmax; P staged through smem to become A operand of P@V.
namespace fa {
constexpr int BQ  = 128;
constexpr int BKV = 64;
constexpr int LDK = 68;   // (4*grp + tg) mod 32 -> conflict-free B-frag reads
constexpr int LDV = 72;   // (8*tg + grp) mod 32 -> conflict-free B-frag reads
constexpr int LDP = 68;
constexpr int SMEM_FLOATS = 2 * BKV * LDK + 2 * BKV * LDV + BQ * LDP;
constexpr int SMEM_BYTES  = SMEM_FLOATS * 4;   // 106496
}

__global__ void __launch_bounds__(256, 1) flash_attn(
    const float* __restrict__ Q, const float* __restrict__ K,
    const float* __restrict__ V, float* __restrict__ O)
{
    using namespace fa;
    extern __shared__ float sm[];
    float* Ks = sm;
    float* Vs = sm + 2 * BKV * LDK;
    float* Ps = sm + 2 * BKV * LDK + 2 * BKV * LDV;

    const int tid  = threadIdx.x;
    const int lane = tid & 31;
    const int warp = tid >> 5;
    const int grp  = lane >> 2;
    const int tg   = lane & 3;
    const int bh   = blockIdx.y;
    const int b    = bh >> 4;
    const int h    = bh & 15;
    const long long base = (long long)b * ((long long)cfg::SEQ * cfg::D_MODEL)
                         + (long long)h * cfg::HDIM;
    const float* Qp = Q + base;
    const float* Kp = K + base;
    const float* Vp = V + base;
    const int bm   = blockIdx.x * BQ;
    const int wrow = warp * 16;

    // ---- stage Q tile (pre-scaled, tf32) via Ps, read persistent fragments ----
    {
        const int r = tid >> 4;
        const int c = (tid & 15) << 2;
        #pragma unroll
        for (int i = 0; i < 8; i++) {
            int row = r + i * 16;
            float4 qv = *reinterpret_cast<const float4*>(
                Qp + (long long)(bm + row) * cfg::D_MODEL + c);
            uint32_t* d = reinterpret_cast<uint32_t*>(&Ps[row * LDP + c]);
            d[0] = f2tf32(qv.x * 0.125f); d[1] = f2tf32(qv.y * 0.125f);
            d[2] = f2tf32(qv.z * 0.125f); d[3] = f2tf32(qv.w * 0.125f);
        }
    }
    __syncthreads();
    uint32_t qf[8][4];
    #pragma unroll
    for (int kk = 0; kk < 8; kk++) {
        qf[kk][0] = __float_as_uint(Ps[(wrow + grp    ) * LDP + kk * 8 + tg    ]);
        qf[kk][1] = __float_as_uint(Ps[(wrow + grp + 8) * LDP + kk * 8 + tg    ]);
        qf[kk][2] = __float_as_uint(Ps[(wrow + grp    ) * LDP + kk * 8 + tg + 4]);
        qf[kk][3] = __float_as_uint(Ps[(wrow + grp + 8) * LDP + kk * 8 + tg + 4]);
    }
    __syncthreads();

    // ---- KV tile loaders (reg prefetch + smem double buffer) ----
    float4 rk[4], rv[4];
    const int kr = tid >> 4;
    const int kc = (tid & 15) << 2;
    auto ldg_kv = [&](int t) {
        #pragma unroll
        for (int i = 0; i < 4; i++) {
            long long row = (long long)(t * BKV + kr + i * 16);
            rk[i] = *reinterpret_cast<const float4*>(Kp + row * cfg::D_MODEL + kc);
            rv[i] = *reinterpret_cast<const float4*>(Vp + row * cfg::D_MODEL + kc);
        }
    };
    auto sts_kv = [&](int bf) {
        #pragma unroll
        for (int i = 0; i < 4; i++) {
            int row = kr + i * 16;
            uint32_t* dk = reinterpret_cast<uint32_t*>(&Ks[(bf * BKV + row) * LDK + kc]);
            dk[0] = f2tf32(rk[i].x); dk[1] = f2tf32(rk[i].y);
            dk[2] = f2tf32(rk[i].z); dk[3] = f2tf32(rk[i].w);
            uint32_t* dv = reinterpret_cast<uint32_t*>(&Vs[(bf * BKV + row) * LDV + kc]);
            dv[0] = f2tf32(rv[i].x); dv[1] = f2tf32(rv[i].y);
            dv[2] = f2tf32(rv[i].z); dv[3] = f2tf32(rv[i].w);
        }
    };

    float oacc[8][4];
    #pragma unroll
    for (int ni = 0; ni < 8; ni++)
        #pragma unroll
        for (int j = 0; j < 4; j++) oacc[ni][j] = 0.f;
    float m0 = -3.402823466e38f, m1 = -3.402823466e38f;
    float l0 = 0.f, l1 = 0.f;

    constexpr int NT = cfg::SEQ / BKV;   // 32
    ldg_kv(0);
    sts_kv(0);
    __syncthreads();
    int buf = 0;

    for (int t = 0; t < NT; t++) {
        if (t + 1 < NT) ldg_kv(t + 1);

        // ---- S = (Q/8) @ K^T ----
        float sacc[8][4];
        #pragma unroll
        for (int ni = 0; ni < 8; ni++)
            #pragma unroll
            for (int j = 0; j < 4; j++) sacc[ni][j] = 0.f;

        const float* Kb = Ks + buf * BKV * LDK;
        #pragma unroll
        for (int kk = 0; kk < 8; kk++) {
            #pragma unroll
            for (int ni = 0; ni < 8; ni++) {
                uint32_t bb[2] = {
                    __float_as_uint(Kb[(ni * 8 + grp) * LDK + kk * 8 + tg    ]),
                    __float_as_uint(Kb[(ni * 8 + grp) * LDK + kk * 8 + tg + 4])};
                mma_m16n8k8(sacc[ni], qf[kk], bb);
            }
        }

        // ---- online softmax (rows grp and grp+8 of this warp) ----
        float mx0 = -3.402823466e38f, mx1 = -3.402823466e38f;
        #pragma unroll
        for (int ni = 0; ni < 8; ni++) {
            mx0 = fmaxf(mx0, fmaxf(sacc[ni][0], sacc[ni][1]));
            mx1 = fmaxf(mx1, fmaxf(sacc[ni][2], sacc[ni][3]));
        }
        mx0 = fmaxf(mx0, __shfl_xor_sync(0xffffffffu, mx0, 1));
        mx0 = fmaxf(mx0, __shfl_xor_sync(0xffffffffu, mx0, 2));
        mx1 = fmaxf(mx1, __shfl_xor_sync(0xffffffffu, mx1, 1));
        mx1 = fmaxf(mx1, __shfl_xor_sync(0xffffffffu, mx1, 2));

        const float mn0 = fmaxf(m0, mx0);
        const float mn1 = fmaxf(m1, mx1);
        const float a0  = __expf(m0 - mn0);
        const float a1  = __expf(m1 - mn1);
        m0 = mn0; m1 = mn1;

        float rs0 = 0.f, rs1 = 0.f;
        #pragma unroll
        for (int ni = 0; ni < 8; ni++) {
            float p0 = __expf(sacc[ni][0] - m0);
            float p1 = __expf(sacc[ni][1] - m0);
            float p2 = __expf(sacc[ni][2] - m1);
            float p3 = __expf(sacc[ni][3] - m1);
            rs0 += p0 + p1;
            rs1 += p2 + p3;
            const int c = ni * 8 + tg * 2;
            uint32_t* w0 = reinterpret_cast<uint32_t*>(&Ps[(wrow + grp) * LDP + c]);
            w0[0] = f2tf32(p0); w0[1] = f2tf32(p1);
            uint32_t* w1 = reinterpret_cast<uint32_t*>(&Ps[(wrow + grp + 8) * LDP + c]);
            w1[0] = f2tf32(p2); w1[1] = f2tf32(p3);
        }
        l0 = l0 * a0 + rs0;
        l1 = l1 * a1 + rs1;
        #pragma unroll
        for (int ni = 0; ni < 8; ni++) {
            oacc[ni][0] *= a0; oacc[ni][1] *= a0;
            oacc[ni][2] *= a1; oacc[ni][3] *= a1;
        }
        __syncwarp();

        // ---- O += P @ V ----
        const float* Vb = Vs + buf * BKV * LDV;
        #pragma unroll
        for (int kk = 0; kk < 8; kk++) {
            uint32_t af[4];
            af[0] = __float_as_uint(Ps[(wrow + grp    ) * LDP + kk * 8 + tg    ]);
            af[1] = __float_as_uint(Ps[(wrow + grp + 8) * LDP + kk * 8 + tg    ]);
            af[2] = __float_as_uint(Ps[(wrow + grp    ) * LDP + kk * 8 + tg + 4]);
            af[3] = __float_as_uint(Ps[(wrow + grp + 8) * LDP + kk * 8 + tg + 4]);
            #pragma unroll
            for (int ni = 0; ni < 8; ni++) {
                uint32_t bb[2] = {
                    __float_as_uint(Vb[(kk * 8 + tg    ) * LDV + ni * 8 + grp]),
                    __float_as_uint(Vb[(kk * 8 + tg + 4) * LDV + ni * 8 + grp])};
                mma_m16n8k8(oacc[ni], af, bb);
            }
        }

        if (t + 1 < NT) sts_kv(buf ^ 1);
        __syncthreads();
        buf ^= 1;
    }

    // ---- epilogue: normalize and store ----
    l0 += __shfl_xor_sync(0xffffffffu, l0, 1);
    l0 += __shfl_xor_sync(0xffffffffu, l0, 2);
    l1 += __shfl_xor_sync(0xffffffffu, l1, 1);
    l1 += __shfl_xor_sync(0xffffffffu, l1, 2);
    const float inv0 = 1.f / l0;
    const float inv1 = 1.f / l1;

    const long long tok0 = (long long)b * cfg::SEQ + bm + wrow + grp;
    #pragma unroll
    for (int ni = 0; ni < 8; ni++) {
        const int c = h * cfg::HDIM + ni * 8 + tg * 2;
        *reinterpret_cast<float2*>(&O[tok0 * cfg::D_MODEL + c]) =
            make_float2(oacc[ni][0] * inv0, oacc[ni][1] * inv0);
        *reinterpret_cast<float2*>(&O[(tok0 + 8) * cfg::D_MODEL + c]) =
            make_float2(oacc[ni][2] * inv1, oacc[ni][3] * inv1);
    }
}

// ------------------------------ add + LayerNorm ----------------------------
__global__ void __launch_bounds__(256) add_ln_kernel(
    const float* __restrict__ a, const float* __restrict__ b,
    const float* __restrict__ gamma, const float* __restrict__ beta,
    float* __restrict__ outp)
{
    const long long row = blockIdx.x;
    const float* pa = a + row * cfg::D_MODEL;
    const float* pb = b + row * cfg::D_MODEL;
    float* po = outp + row * cfg::D_MODEL;
    const int tid = threadIdx.x;

    float v[4];
    float s = 0.f, sq = 0.f;
    #pragma unroll
    for (int i = 0; i < 4; i++) {
        const int c = i * 256 + tid;
        v[i] = pa[c] + pb[c];
        s += v[i];
        sq += v[i] * v[i];
    }

    __shared__ float r1[8], r2[8];
    #pragma unroll
    for (int o = 16; o > 0; o >>= 1) {
        s  += __shfl_xor_sync(0xffffffffu, s, o);
        sq += __shfl_xor_sync(0xffffffffu, sq, o);
    }
    if ((tid & 31) == 0) { r1[tid >> 5] = s; r2[tid >> 5] = sq; }
    __syncthreads();
    s = 0.f; sq = 0.f;
    #pragma unroll
    for (int j = 0; j < 8; j++) { s += r1[j]; sq += r2[j]; }

    const float mu   = s * (1.f / cfg::D_MODEL);
    const float var  = sq * (1.f / cfg::D_MODEL) - mu * mu;
    const float rstd = rsqrtf(var + 1e-5f);

    #pragma unroll
    for (int i = 0; i < 4; i++) {
        const int c = i * 256 + tid;
        po[c] = (v[i] - mu) * rstd * __ldg(&gamma[c]) + __ldg(&beta[c]);
    }
}

// ------------------------------ launch -------------------------------------
extern "C" void kernel_launch(void* const* d_in, const int* in_sizes, int n_in,
                              void* d_out, int out_size)
{
    using namespace cfg;
    const float* x   = (const float*)d_in[0];
    const float* Wq  = (const float*)d_in[1];
    const float* bq  = (const float*)d_in[2];
    const float* Wk  = (const float*)d_in[3];
    const float* bk_ = (const float*)d_in[4];
    const float* Wv  = (const float*)d_in[5];
    const float* bv  = (const float*)d_in[6];
    const float* Wo  = (const float*)d_in[7];
    const float* bo  = (const float*)d_in[8];
    const float* W1  = (const float*)d_in[9];
    const float* b1  = (const float*)d_in[10];
    const float* W2  = (const float*)d_in[11];
    const float* b2  = (const float*)d_in[12];
    const float* g1  = (const float*)d_in[13];
    const float* be1 = (const float*)d_in[14];
    const float* g2  = (const float*)d_in[15];
    const float* be2 = (const float*)d_in[16];
    float* out = (float*)d_out;

    float *q, *k, *v, *attn, *h, *ff;
    cudaGetSymbolAddress((void**)&q,    g_q);
    cudaGetSymbolAddress((void**)&k,    g_k);
    cudaGetSymbolAddress((void**)&v,    g_v);
    cudaGetSymbolAddress((void**)&attn, g_attn);
    cudaGetSymbolAddress((void**)&h,    g_h);
    cudaGetSymbolAddress((void**)&ff,   g_ff);

    static bool attr_done = false;
    if (!attr_done) {
        cudaFuncSetAttribute(flash_attn,
                             cudaFuncAttributeMaxDynamicSharedMemorySize,
                             fa::SMEM_BYTES);
        attr_done = true;
    }

    // 1) Q/K/V projections
    {
        dim3 grid(D_MODEL / 128, NTOK / 128, 1);
        gemm_tf32<128,128,16,64,32,false,false><<<grid, 256>>>(
            x, Wq, bq, q, NTOK, D_MODEL, D_MODEL, D_MODEL, D_MODEL, D_MODEL,
            1, 0, 0, 0, 0, 0, 0, 1.f);
        gemm_tf32<128,128,16,64,32,false,false><<<grid, 256>>>(
            x, Wk, bk_, k, NTOK, D_MODEL, D_MODEL, D_MODEL, D_MODEL, D_MODEL,
            1, 0, 0, 0, 0, 0, 0, 1.f);
        gemm_tf32<128,128,16,64,32,false,false><<<grid, 256>>>(
            x, Wv, bv, v, NTOK, D_MODEL, D_MODEL, D_MODEL, D_MODEL, D_MODEL,
            1, 0, 0, 0, 0, 0, 0, 1.f);
    }

    // 2-4) fused flash attention -> attn
    {
        dim3 grid(SEQ / fa::BQ, BATCH * NHEADS);
        flash_attn<<<grid, 256, fa::SMEM_BYTES>>>(q, k, v, attn);
    }

    // 5) output projection: attn @ Wo + bo  -> reuse q as scratch
    {
        dim3 grid(D_MODEL / 128, NTOK / 128, 1);
        gemm_tf32<128,128,16,64,32,false,false><<<grid, 256>>>(
            attn, Wo, bo, q, NTOK, D_MODEL, D_MODEL, D_MODEL, D_MODEL, D_MODEL,
            1, 0, 0, 0, 0, 0, 0, 1.f);
    }

    // 6) h = LN(x + proj)
    add_ln_kernel<<<NTOK, 256>>>(x, q, g1, be1, h);

    // 7) ff = relu(h @ W1 + b1)
    {
        dim3 grid(DFF / 128, NTOK / 128, 1);
        gemm_tf32<128,128,16,64,32,false,true><<<grid, 256>>>(
            h, W1, b1, ff, NTOK, DFF, D_MODEL, D_MODEL, DFF, DFF,
            1, 0, 0, 0, 0, 0, 0, 1.f);
    }

    // 8) ff2 = ff @ W2 + b2  -> reuse k as scratch
    {
        dim3 grid(D_MODEL / 128, NTOK / 128, 1);
        gemm_tf32<128,128,16,64,32,false,false><<<grid, 256>>>(
            ff, W2, b2, k, NTOK, D_MODEL, DFF, DFF, D_MODEL, D_MODEL,
            1, 0, 0, 0, 0, 0, 0, 1.f);
    }

    // 9) out = LN(h + ff2)
    add_ln_kernel<<<NTOK, 256>>>(h, k, g2, be2, out);
}

// round 3
// speedup vs baseline: 1.5607x; 1.2607x over previous
#include <cuda_runtime.h>
#include <cstdint>

// ---------------------------------------------------------------------------
// EncoderLayer: x -> MHA(flash) -> add&LN -> FF(relu) -> add&LN
// B=4, S=2048, D=1024, H=16, hd=64, FF=4096, fp32 in/out.
// Round 3: cp.async 3-stage GEMM + cp.async flash-attention, raw-fp32->tf32.
// ---------------------------------------------------------------------------

namespace cfg {
constexpr int D_MODEL = 1024;
constexpr int NHEADS  = 16;
constexpr int HDIM    = 64;
constexpr int DFF     = 4096;
constexpr int BATCH   = 4;
constexpr int SEQ     = 2048;
constexpr int NTOK    = BATCH * SEQ;   // 8192
}

// ------------------------------ scratch ------------------------------------
__device__ float g_q   [(size_t)cfg::NTOK * cfg::D_MODEL];
__device__ float g_k   [(size_t)cfg::NTOK * cfg::D_MODEL];
__device__ float g_v   [(size_t)cfg::NTOK * cfg::D_MODEL];
__device__ float g_attn[(size_t)cfg::NTOK * cfg::D_MODEL];
__device__ float g_h   [(size_t)cfg::NTOK * cfg::D_MODEL];
__device__ float g_ff  [(size_t)cfg::NTOK * cfg::DFF];

// ------------------------------ helpers ------------------------------------
__device__ __forceinline__ void cp16(void* s, const void* g) {
    uint32_t sa = (uint32_t)__cvta_generic_to_shared(s);
    asm volatile("cp.async.cg.shared.global [%0], [%1], 16;\n" :: "r"(sa), "l"(g));
}
__device__ __forceinline__ void cp_commit() {
    asm volatile("cp.async.commit_group;\n");
}
template <int N>
__device__ __forceinline__ void cp_wait() {
    asm volatile("cp.async.wait_group %0;\n" :: "n"(N));
}

// mma with raw fp32 operands interpreted as tf32 (RZ truncation in HW).
__device__ __forceinline__ void mma_m16n8k8(float* c, const uint32_t* a, const uint32_t* b) {
    asm volatile(
        "mma.sync.aligned.m16n8k8.row.col.f32.tf32.tf32.f32 "
        "{%0,%1,%2,%3}, {%4,%5,%6,%7}, {%8,%9}, {%0,%1,%2,%3};\n"
        : "+f"(c[0]), "+f"(c[1]), "+f"(c[2]), "+f"(c[3])
        : "r"(a[0]), "r"(a[1]), "r"(a[2]), "r"(a[3]),
          "r"(b[0]), "r"(b[1]));
}

// ------------------------------ GEMM (cp.async) -----------------------------
// C[M,N] = alpha * A[M,K] @ B[K,N] + bias, optional ReLU. Row-major, lda=K,
// ldb=N, ldc=N. M,N multiples of 128; K multiple of 32.
namespace gg {
constexpr int BM = 128, BN = 128, BK = 32, STG = 3;
constexpr int LDA = 36;    // 4*grp+tg = lane -> conflict-free A frag reads
constexpr int LDB = 136;   // 8*tg+grp -> conflict-free B frag reads
constexpr int STAGE_FLOATS = BM * LDA + BK * LDB;   // 4608+4352 = 8960
constexpr int SMEM_BYTES = STG * STAGE_FLOATS * 4;  // 107520
}

template <bool RELU>
__global__ void __launch_bounds__(256) gemm_cp(
    const float* __restrict__ A, const float* __restrict__ B,
    const float* __restrict__ bias, float* __restrict__ C,
    int N, int K, float alpha)
{
    using namespace gg;
    extern __shared__ float sm[];

    const int tid  = threadIdx.x;
    const int lane = tid & 31;
    const int warp = tid >> 5;
    const int wm   = warp & 1;          // 2 warps along M (64 each)
    const int wn   = warp >> 1;         // 4 warps along N (32 each)
    const int grp  = lane >> 2;
    const int tg   = lane & 3;
    const int bm   = blockIdx.y * BM;
    const int bn   = blockIdx.x * BN;

    // cp.async thread mapping
    const int at_row = tid >> 3;            // 0..31, +i*32
    const int at_col = (tid & 7) << 2;      // 0..28
    const int bt_row = tid >> 5;            // 0..7, +i*8
    const int bt_col = (tid & 31) << 2;     // 0..124

    auto issue = [&](int kt, int stg) {
        float* sA = sm + stg * STAGE_FLOATS;
        float* sB = sA + BM * LDA;
        const int k0 = kt * BK;
        #pragma unroll
        for (int i = 0; i < 4; i++) {
            int r = at_row + i * 32;
            cp16(&sA[r * LDA + at_col],
                 &A[(size_t)(bm + r) * K + k0 + at_col]);
        }
        #pragma unroll
        for (int i = 0; i < 4; i++) {
            int r = bt_row + i * 8;
            cp16(&sB[r * LDB + bt_col],
                 &B[(size_t)(k0 + r) * N + bn + bt_col]);
        }
    };

    float acc[4][4][4];
    #pragma unroll
    for (int mi = 0; mi < 4; mi++)
        #pragma unroll
        for (int ni = 0; ni < 4; ni++)
            #pragma unroll
            for (int j = 0; j < 4; j++) acc[mi][ni][j] = 0.f;

    const int ntiles = K / BK;
    issue(0, 0); cp_commit();
    issue(1, 1); cp_commit();

    for (int kt = 0; kt < ntiles; kt++) {
        cp_wait<1>();
        __syncthreads();
        if (kt + 2 < ntiles) issue(kt + 2, (kt + 2) % STG);
        cp_commit();

        const float* sA = sm + (kt % STG) * STAGE_FLOATS;
        const float* sB = sA + BM * LDA;

        #pragma unroll
        for (int kk = 0; kk < BK; kk += 8) {
            uint32_t af[4][4];
            uint32_t bf[4][2];
            #pragma unroll
            for (int mi = 0; mi < 4; mi++) {
                const int r = wm * 64 + mi * 16;
                af[mi][0] = __float_as_uint(sA[(r + grp    ) * LDA + kk + tg    ]);
                af[mi][1] = __float_as_uint(sA[(r + grp + 8) * LDA + kk + tg    ]);
                af[mi][2] = __float_as_uint(sA[(r + grp    ) * LDA + kk + tg + 4]);
                af[mi][3] = __float_as_uint(sA[(r + grp + 8) * LDA + kk + tg + 4]);
            }
            #pragma unroll
            for (int ni = 0; ni < 4; ni++) {
                const int c = wn * 32 + ni * 8 + grp;
                bf[ni][0] = __float_as_uint(sB[(kk + tg    ) * LDB + c]);
                bf[ni][1] = __float_as_uint(sB[(kk + tg + 4) * LDB + c]);
            }
            #pragma unroll
            for (int mi = 0; mi < 4; mi++)
                #pragma unroll
                for (int ni = 0; ni < 4; ni++)
                    mma_m16n8k8(acc[mi][ni], af[mi], bf[ni]);
        }
    }
    __syncthreads();

    #pragma unroll
    for (int mi = 0; mi < 4; mi++) {
        const int r0 = bm + wm * 64 + mi * 16 + grp;
        #pragma unroll
        for (int ni = 0; ni < 4; ni++) {
            const int c0 = bn + wn * 32 + ni * 8 + tg * 2;
            float bv0 = 0.f, bv1 = 0.f;
            if (bias) { bv0 = __ldg(&bias[c0]); bv1 = __ldg(&bias[c0 + 1]); }
            float v0 = acc[mi][ni][0] * alpha + bv0;
            float v1 = acc[mi][ni][1] * alpha + bv1;
            float v2 = acc[mi][ni][2] * alpha + bv0;
            float v3 = acc[mi][ni][3] * alpha + bv1;
            if (RELU) {
                v0 = fmaxf(v0, 0.f); v1 = fmaxf(v1, 0.f);
                v2 = fmaxf(v2, 0.f); v3 = fmaxf(v3, 0.f);
            }
            *reinterpret_cast<float2*>(&C[(size_t)r0 * N + c0]) =
                make_float2(v0, v1);
            *reinterpret_cast<float2*>(&C[(size_t)(r0 + 8) * N + c0]) =
                make_float2(v2, v3);
        }
    }
}

// --------------------------- flash attention --------------------------------
// One CTA = 128 Q rows of one (b,h). 8 warps x 16 rows. KV tiles of 64,
// double-buffered via cp.async. All tensor operands raw fp32 -> tf32.
namespace fa {
constexpr int BQ  = 128;
constexpr int BKV = 64;
constexpr int LDK = 68;
constexpr int LDV = 72;
constexpr int LDP = 68;
constexpr int SMEM_FLOATS = 2 * BKV * LDK + 2 * BKV * LDV + BQ * LDP;
constexpr int SMEM_BYTES  = SMEM_FLOATS * 4;   // 106496
}

__global__ void __launch_bounds__(256, 1) flash_attn(
    const float* __restrict__ Q, const float* __restrict__ K,
    const float* __restrict__ V, float* __restrict__ O)
{
    using namespace fa;
    extern __shared__ float sm[];
    float* Ks = sm;
    float* Vs = sm + 2 * BKV * LDK;
    float* Ps = sm + 2 * BKV * LDK + 2 * BKV * LDV;

    const int tid  = threadIdx.x;
    const int lane = tid & 31;
    const int warp = tid >> 5;
    const int grp  = lane >> 2;
    const int tg   = lane & 3;
    const int bh   = blockIdx.y;
    const int b    = bh >> 4;
    const int h    = bh & 15;
    const long long base = (long long)b * ((long long)cfg::SEQ * cfg::D_MODEL)
                         + (long long)h * cfg::HDIM;
    const float* Qp = Q + base;
    const float* Kp = K + base;
    const float* Vp = V + base;
    const int bm   = blockIdx.x * BQ;
    const int wrow = warp * 16;

    const int kr = tid >> 4;           // 0..15
    const int kc = (tid & 15) << 2;    // 0..60

    auto issue_kv = [&](int t, int bf) {
        #pragma unroll
        for (int i = 0; i < 4; i++) {
            int row = kr + i * 16;
            long long grow = (long long)(t * BKV + row) * cfg::D_MODEL + kc;
            cp16(&Ks[(bf * BKV + row) * LDK + kc], Kp + grow);
            cp16(&Vs[(bf * BKV + row) * LDV + kc], Vp + grow);
        }
    };

    issue_kv(0, 0); cp_commit();

    // ---- stage Q tile (x 1/8, raw fp32) via Ps, read persistent fragments ----
    {
        #pragma unroll
        for (int i = 0; i < 8; i++) {
            int row = kr + i * 16;
            float4 qv = *reinterpret_cast<const float4*>(
                Qp + (long long)(bm + row) * cfg::D_MODEL + kc);
            float* d = &Ps[row * LDP + kc];
            d[0] = qv.x * 0.125f; d[1] = qv.y * 0.125f;
            d[2] = qv.z * 0.125f; d[3] = qv.w * 0.125f;
        }
    }
    __syncthreads();
    uint32_t qf[8][4];
    #pragma unroll
    for (int kk = 0; kk < 8; kk++) {
        qf[kk][0] = __float_as_uint(Ps[(wrow + grp    ) * LDP + kk * 8 + tg    ]);
        qf[kk][1] = __float_as_uint(Ps[(wrow + grp + 8) * LDP + kk * 8 + tg    ]);
        qf[kk][2] = __float_as_uint(Ps[(wrow + grp    ) * LDP + kk * 8 + tg + 4]);
        qf[kk][3] = __float_as_uint(Ps[(wrow + grp + 8) * LDP + kk * 8 + tg + 4]);
    }

    float oacc[8][4];
    #pragma unroll
    for (int ni = 0; ni < 8; ni++)
        #pragma unroll
        for (int j = 0; j < 4; j++) oacc[ni][j] = 0.f;
    float m0 = -3.402823466e38f, m1 = -3.402823466e38f;
    float l0 = 0.f, l1 = 0.f;

    constexpr int NT = cfg::SEQ / BKV;   // 32
    for (int t = 0; t < NT; t++) {
        cp_wait<0>();
        __syncthreads();
        if (t + 1 < NT) issue_kv(t + 1, (t + 1) & 1);
        cp_commit();

        const int buf = t & 1;

        // ---- S = (Q/8) @ K^T ----
        float sacc[8][4];
        #pragma unroll
        for (int ni = 0; ni < 8; ni++)
            #pragma unroll
            for (int j = 0; j < 4; j++) sacc[ni][j] = 0.f;

        const float* Kb = Ks + buf * BKV * LDK;
        #pragma unroll
        for (int kk = 0; kk < 8; kk++) {
            #pragma unroll
            for (int ni = 0; ni < 8; ni++) {
                uint32_t bb[2] = {
                    __float_as_uint(Kb[(ni * 8 + grp) * LDK + kk * 8 + tg    ]),
                    __float_as_uint(Kb[(ni * 8 + grp) * LDK + kk * 8 + tg + 4])};
                mma_m16n8k8(sacc[ni], qf[kk], bb);
            }
        }

        // ---- online softmax (rows grp and grp+8 of this warp) ----
        float mx0 = -3.402823466e38f, mx1 = -3.402823466e38f;
        #pragma unroll
        for (int ni = 0; ni < 8; ni++) {
            mx0 = fmaxf(mx0, fmaxf(sacc[ni][0], sacc[ni][1]));
            mx1 = fmaxf(mx1, fmaxf(sacc[ni][2], sacc[ni][3]));
        }
        mx0 = fmaxf(mx0, __shfl_xor_sync(0xffffffffu, mx0, 1));
        mx0 = fmaxf(mx0, __shfl_xor_sync(0xffffffffu, mx0, 2));
        mx1 = fmaxf(mx1, __shfl_xor_sync(0xffffffffu, mx1, 1));
        mx1 = fmaxf(mx1, __shfl_xor_sync(0xffffffffu, mx1, 2));

        const float mn0 = fmaxf(m0, mx0);
        const float mn1 = fmaxf(m1, mx1);
        const float a0  = __expf(m0 - mn0);
        const float a1  = __expf(m1 - mn1);
        m0 = mn0; m1 = mn1;

        float rs0 = 0.f, rs1 = 0.f;
        #pragma unroll
        for (int ni = 0; ni < 8; ni++) {
            float p0 = __expf(sacc[ni][0] - m0);
            float p1 = __expf(sacc[ni][1] - m0);
            float p2 = __expf(sacc[ni][2] - m1);
            float p3 = __expf(sacc[ni][3] - m1);
            rs0 += p0 + p1;
            rs1 += p2 + p3;
            const int c = ni * 8 + tg * 2;
            float* w0 = &Ps[(wrow + grp) * LDP + c];
            w0[0] = p0; w0[1] = p1;
            float* w1 = &Ps[(wrow + grp + 8) * LDP + c];
            w1[0] = p2; w1[1] = p3;
        }
        l0 = l0 * a0 + rs0;
        l1 = l1 * a1 + rs1;
        #pragma unroll
        for (int ni = 0; ni < 8; ni++) {
            oacc[ni][0] *= a0; oacc[ni][1] *= a0;
            oacc[ni][2] *= a1; oacc[ni][3] *= a1;
        }
        __syncwarp();

        // ---- O += P @ V ----
        const float* Vb = Vs + buf * BKV * LDV;
        #pragma unroll
        for (int kk = 0; kk < 8; kk++) {
            uint32_t af[4];
            af[0] = __float_as_uint(Ps[(wrow + grp    ) * LDP + kk * 8 + tg    ]);
            af[1] = __float_as_uint(Ps[(wrow + grp + 8) * LDP + kk * 8 + tg    ]);
            af[2] = __float_as_uint(Ps[(wrow + grp    ) * LDP + kk * 8 + tg + 4]);
            af[3] = __float_as_uint(Ps[(wrow + grp + 8) * LDP + kk * 8 + tg + 4]);
            #pragma unroll
            for (int ni = 0; ni < 8; ni++) {
                uint32_t bb[2] = {
                    __float_as_uint(Vb[(kk * 8 + tg    ) * LDV + ni * 8 + grp]),
                    __float_as_uint(Vb[(kk * 8 + tg + 4) * LDV + ni * 8 + grp])};
                mma_m16n8k8(oacc[ni], af, bb);
            }
        }
    }

    // ---- epilogue: normalize and store ----
    l0 += __shfl_xor_sync(0xffffffffu, l0, 1);
    l0 += __shfl_xor_sync(0xffffffffu, l0, 2);
    l1 += __shfl_xor_sync(0xffffffffu, l1, 1);
    l1 += __shfl_xor_sync(0xffffffffu, l1, 2);
    const float inv0 = 1.f / l0;
    const float inv1 = 1.f / l1;

    const long long tok0 = (long long)b * cfg::SEQ + bm + wrow + grp;
    #pragma unroll
    for (int ni = 0; ni < 8; ni++) {
        const int c = h * cfg::HDIM + ni * 8 + tg * 2;
        *reinterpret_cast<float2*>(&O[tok0 * cfg::D_MODEL + c]) =
            make_float2(oacc[ni][0] * inv0, oacc[ni][1] * inv0);
        *reinterpret_cast<float2*>(&O[(tok0 + 8) * cfg::D_MODEL + c]) =
            make_float2(oacc[ni][2] * inv1, oacc[ni][3] * inv1);
    }
}

// ------------------------------ add + LayerNorm ----------------------------
__global__ void __launch_bounds__(256) add_ln_kernel(
    const float* __restrict__ a, const float* __restrict__ b,
    const float* __restrict__ gamma, const float* __restrict__ beta,
    float* __restrict__ outp)
{
    const long long row = blockIdx.x;
    const float* pa = a + row * cfg::D_MODEL;
    const float* pb = b + row * cfg::D_MODEL;
    float* po = outp + row * cfg::D_MODEL;
    const int tid = threadIdx.x;

    float v[4];
    float s = 0.f, sq = 0.f;
    #pragma unroll
    for (int i = 0; i < 4; i++) {
        const int c = i * 256 + tid;
        v[i] = pa[c] + pb[c];
        s += v[i];
        sq += v[i] * v[i];
    }

    __shared__ float r1[8], r2[8];
    #pragma unroll
    for (int o = 16; o > 0; o >>= 1) {
        s  += __shfl_xor_sync(0xffffffffu, s, o);
        sq += __shfl_xor_sync(0xffffffffu, sq, o);
    }
    if ((tid & 31) == 0) { r1[tid >> 5] = s; r2[tid >> 5] = sq; }
    __syncthreads();
    s = 0.f; sq = 0.f;
    #pragma unroll
    for (int j = 0; j < 8; j++) { s += r1[j]; sq += r2[j]; }

    const float mu   = s * (1.f / cfg::D_MODEL);
    const float var  = sq * (1.f / cfg::D_MODEL) - mu * mu;
    const float rstd = rsqrtf(var + 1e-5f);

    #pragma unroll
    for (int i = 0; i < 4; i++) {
        const int c = i * 256 + tid;
        po[c] = (v[i] - mu) * rstd * __ldg(&gamma[c]) + __ldg(&beta[c]);
    }
}

// ------------------------------ launch -------------------------------------
extern "C" void kernel_launch(void* const* d_in, const int* in_sizes, int n_in,
                              void* d_out, int out_size)
{
    using namespace cfg;
    const float* x   = (const float*)d_in[0];
    const float* Wq  = (const float*)d_in[1];
    const float* bq  = (const float*)d_in[2];
    const float* Wk  = (const float*)d_in[3];
    const float* bk_ = (const float*)d_in[4];
    const float* Wv  = (const float*)d_in[5];
    const float* bv  = (const float*)d_in[6];
    const float* Wo  = (const float*)d_in[7];
    const float* bo  = (const float*)d_in[8];
    const float* W1  = (const float*)d_in[9];
    const float* b1  = (const float*)d_in[10];
    const float* W2  = (const float*)d_in[11];
    const float* b2  = (const float*)d_in[12];
    const float* g1  = (const float*)d_in[13];
    const float* be1 = (const float*)d_in[14];
    const float* g2  = (const float*)d_in[15];
    const float* be2 = (const float*)d_in[16];
    float* out = (float*)d_out;

    float *q, *k, *v, *attn, *h, *ff;
    cudaGetSymbolAddress((void**)&q,    g_q);
    cudaGetSymbolAddress((void**)&k,    g_k);
    cudaGetSymbolAddress((void**)&v,    g_v);
    cudaGetSymbolAddress((void**)&attn, g_attn);
    cudaGetSymbolAddress((void**)&h,    g_h);
    cudaGetSymbolAddress((void**)&ff,   g_ff);

    static bool attr_done = false;
    if (!attr_done) {
        cudaFuncSetAttribute(flash_attn,
                             cudaFuncAttributeMaxDynamicSharedMemorySize,
                             fa::SMEM_BYTES);
        cudaFuncSetAttribute(gemm_cp<false>,
                             cudaFuncAttributeMaxDynamicSharedMemorySize,
                             gg::SMEM_BYTES);
        cudaFuncSetAttribute(gemm_cp<true>,
                             cudaFuncAttributeMaxDynamicSharedMemorySize,
                             gg::SMEM_BYTES);
        attr_done = true;
    }

    // 1) Q/K/V projections: [8192,1024] @ [1024,1024] + bias
    {
        dim3 grid(D_MODEL / 128, NTOK / 128);
        gemm_cp<false><<<grid, 256, gg::SMEM_BYTES>>>(x, Wq, bq, q, D_MODEL, D_MODEL, 1.f);
        gemm_cp<false><<<grid, 256, gg::SMEM_BYTES>>>(x, Wk, bk_, k, D_MODEL, D_MODEL, 1.f);
        gemm_cp<false><<<grid, 256, gg::SMEM_BYTES>>>(x, Wv, bv, v, D_MODEL, D_MODEL, 1.f);
    }

    // 2-4) fused flash attention -> attn
    {
        dim3 grid(SEQ / fa::BQ, BATCH * NHEADS);
        flash_attn<<<grid, 256, fa::SMEM_BYTES>>>(q, k, v, attn);
    }

    // 5) output projection: attn @ Wo + bo -> reuse q
    {
        dim3 grid(D_MODEL / 128, NTOK / 128);
        gemm_cp<false><<<grid, 256, gg::SMEM_BYTES>>>(attn, Wo, bo, q, D_MODEL, D_MODEL, 1.f);
    }

    // 6) h = LN(x + proj)
    add_ln_kernel<<<NTOK, 256>>>(x, q, g1, be1, h);

    // 7) ff = relu(h @ W1 + b1)
    {
        dim3 grid(DFF / 128, NTOK / 128);
        gemm_cp<true><<<grid, 256, gg::SMEM_BYTES>>>(h, W1, b1, ff, DFF, D_MODEL, 1.f);
    }

    // 8) ff2 = ff @ W2 + b2 -> reuse k
    {
        dim3 grid(D_MODEL / 128, NTOK / 128);
        gemm_cp<false><<<grid, 256, gg::SMEM_BYTES>>>(ff, W2, b2, k, D_MODEL, DFF, 1.f);
    }

    // 9) out = LN(h + ff2)
    add_ln_kernel<<<NTOK, 256>>>(h, k, g2, be2, out);
}